// round 4
// baseline (speedup 1.0000x reference)
#include <cuda_runtime.h>
#include <cuda_bf16.h>
#include <math.h>

#define B    128
#define L    512
#define FIN  128
#define FOUT 128
#define ALPHA 0.2f

// Scratch (device globals — no allocation allowed)
__device__ float g_Wh[(size_t)B * L * FOUT];   // 33.5 MB
__device__ float g_ei[B * L];
__device__ float g_ej[B * L];
__device__ int   g_maskKind;   // 0=int32, 1=uint8, 2=float32

// ---------------------------------------------------------------------------
// Kernel 0: detect adj_mask storage layout (bool dtype on device is unknown).
// 1 warp, 256 words is plenty: float32 -> word0 is 0x3F800000 (diag true);
// uint8 -> ~all words have multiple 0x01 bytes (>1); int32 -> words are 0/1.
// ---------------------------------------------------------------------------
__global__ void k_detect(const unsigned int* __restrict__ m) {
    unsigned gt1 = 0, flt = 0;
    for (int i = threadIdx.x; i < 256; i += 32) {
        unsigned w = m[i];
        if (w == 0x3F800000u) flt = 1;
        else if (w > 1u)      gt1 = 1;
    }
    unsigned bft = __ballot_sync(0xFFFFFFFFu, flt);
    unsigned bgt = __ballot_sync(0xFFFFFFFFu, gt1);
    if (threadIdx.x == 0)
        g_maskKind = bft ? 2 : (bgt ? 1 : 0);
}

// ---------------------------------------------------------------------------
// Kernel 1: Wh = h @ W  (M=65536, K=128, N=128) 128x128 tile, 8x8 micro-tile,
// fused epilogue: ei = Wh@a[:F], ej = Wh@a[F:]  (shuffle-reduced per row).
// ---------------------------------------------------------------------------
#define HT_LD 132

__global__ __launch_bounds__(256, 2) void k_gemm1(const float* __restrict__ h,
                                                  const float* __restrict__ W,
                                                  const float* __restrict__ a) {
    __shared__ float hsT[32][HT_LD];   // transposed h tile: [k][i]
    __shared__ float Ws[32][128];      // [k][n]

    const int t  = threadIdx.x;
    const int tr = t >> 4;
    const int tc = t & 15;

    const long rowBase = (long)blockIdx.x * 128;

    float acc[8][8];
    #pragma unroll
    for (int r = 0; r < 8; r++)
        #pragma unroll
        for (int c = 0; c < 8; c++) acc[r][c] = 0.f;

    for (int kc = 0; kc < FIN; kc += 32) {
        __syncthreads();
        for (int l = t; l < 1024; l += 256) {
            int i = l >> 3, k4 = l & 7;
            float4 v = *(const float4*)(h + (rowBase + i) * FIN + kc + k4 * 4);
            hsT[k4 * 4 + 0][i] = v.x;
            hsT[k4 * 4 + 1][i] = v.y;
            hsT[k4 * 4 + 2][i] = v.z;
            hsT[k4 * 4 + 3][i] = v.w;
        }
        for (int l = t; l < 1024; l += 256) {
            int r = l >> 5, c4 = l & 31;
            *(float4*)&Ws[r][c4 * 4] =
                *(const float4*)(W + (kc + r) * FOUT + c4 * 4);
        }
        __syncthreads();

        #pragma unroll
        for (int k = 0; k < 32; k++) {
            float4 a0 = *(float4*)&hsT[k][tr * 8];
            float4 a1 = *(float4*)&hsT[k][tr * 8 + 4];
            float4 b0 = *(float4*)&Ws[k][tc * 8];
            float4 b1 = *(float4*)&Ws[k][tc * 8 + 4];
            float av[8] = {a0.x, a0.y, a0.z, a0.w, a1.x, a1.y, a1.z, a1.w};
            float bv[8] = {b0.x, b0.y, b0.z, b0.w, b1.x, b1.y, b1.z, b1.w};
            #pragma unroll
            for (int r = 0; r < 8; r++)
                #pragma unroll
                for (int c = 0; c < 8; c++)
                    acc[r][c] = fmaf(av[r], bv[c], acc[r][c]);
        }
    }

    #pragma unroll
    for (int r = 0; r < 8; r++) {
        float* o = g_Wh + (rowBase + tr * 8 + r) * FOUT + tc * 8;
        float4 v0 = {acc[r][0], acc[r][1], acc[r][2], acc[r][3]};
        float4 v1 = {acc[r][4], acc[r][5], acc[r][6], acc[r][7]};
        *(float4*)o       = v0;
        *(float4*)(o + 4) = v1;
    }

    float av1[8], av2[8];
    #pragma unroll
    for (int c = 0; c < 8; c++) {
        av1[c] = a[tc * 8 + c];
        av2[c] = a[FOUT + tc * 8 + c];
    }
    #pragma unroll
    for (int r = 0; r < 8; r++) {
        float s1 = 0.f, s2 = 0.f;
        #pragma unroll
        for (int c = 0; c < 8; c++) {
            s1 = fmaf(acc[r][c], av1[c], s1);
            s2 = fmaf(acc[r][c], av2[c], s2);
        }
        #pragma unroll
        for (int o = 8; o; o >>= 1) {
            s1 += __shfl_xor_sync(0xFFFFFFFFu, s1, o);
            s2 += __shfl_xor_sync(0xFFFFFFFFu, s2, o);
        }
        if (tc == 0) {
            g_ei[rowBase + tr * 8 + r] = s1;
            g_ej[rowBase + tr * 8 + r] = s2;
        }
    }
}

// ---------------------------------------------------------------------------
// Kernel 2: fused attention. Block = (128 i-rows, batch b), streams 8 j-tiles
// of 64. p stored ROW-MAJOR (stride 66): STS conflict-free; GEMM A-operand
// read as broadcast float2 (j-step 2). No online softmax (logits O(+-6));
// unnormalized accumulation, divide + ELU epilogue.
// ---------------------------------------------------------------------------
#define PS_LD 66

__global__ __launch_bounds__(256, 2) void k_attn(const float* __restrict__ bias,
                                                 const void* __restrict__ adj,
                                                 float* __restrict__ out) {
    extern __shared__ float sm[];
    float* Whs = sm;                       // [64][128]
    float* ps  = sm + 64 * 128;            // [128][PS_LD] row-major
    float* eis = ps + 128 * PS_LD;         // [128]

    const int kind = g_maskKind;
    const int* adjI = (const int*)adj;
    const unsigned char* adjB = (const unsigned char*)adj;
    const float* adjF = (const float*)adj;

    const int b  = blockIdx.y;
    const int i0 = blockIdx.x * 128;
    const int t  = threadIdx.x;
    const int tr = t >> 4;                 // rows tr*8..+7
    const int tc = t & 15;                 // cols tc*8..+7

    if (t < 128) eis[t] = g_ei[b * L + i0 + t];

    const float* Whb = g_Wh + (long)b * L * FOUT;
    const float* ejb = g_ej + b * L;

    float acc[8][8];
    #pragma unroll
    for (int r = 0; r < 8; r++)
        #pragma unroll
        for (int c = 0; c < 8; c++) acc[r][c] = 0.f;
    float sreg[8] = {0.f, 0.f, 0.f, 0.f, 0.f, 0.f, 0.f, 0.f};

    const int jj     = t & 63;
    const int iiBase = (t >> 6) * 32;

    for (int jt = 0; jt < 8; jt++) {
        const int j0 = jt * 64;
        __syncthreads();   // previous-iteration smem reads complete

        // Wh tile: 64 rows x 128 cols = 2048 float4
        for (int l = t; l < 2048; l += 256)
            *(float4*)&Whs[l * 4] = *(const float4*)(Whb + j0 * FOUT + l * 4);

        // p tile (row-major store: lanes jj consecutive -> conflict-free STS)
        {
            const float ejv = ejb[j0 + jj];
            const long base = (long)(i0 + iiBase) * L + j0 + jj;
            const float* bRow = bias + (long)b * L * L + base;
            #pragma unroll 8
            for (int q = 0; q < 32; q++) {
                const int ii = iiBase + q;
                float x = eis[ii] + ejv;
                x = x > 0.f ? x : ALPHA * x;
                x += bRow[(long)q * L];
                const long mIdx = base + (long)q * L;
                bool m;
                if (kind == 0)      m = adjI[mIdx] != 0;
                else if (kind == 1) m = adjB[mIdx] != 0;
                else                m = adjF[mIdx] != 0.f;
                ps[ii * PS_LD + jj] = m ? __expf(x) : 0.f;
            }
        }
        __syncthreads();

        // micro-GEMM: acc[128x128] += p[128x64] @ Wh[64x128], j-step 2
        #pragma unroll 4
        for (int j = 0; j < 64; j += 2) {
            float2 pr[8];
            #pragma unroll
            for (int r = 0; r < 8; r++)
                pr[r] = *(float2*)&ps[(tr * 8 + r) * PS_LD + j];

            float4 b00 = *(float4*)&Whs[j * FOUT + tc * 8];
            float4 b01 = *(float4*)&Whs[j * FOUT + tc * 8 + 4];
            float4 b10 = *(float4*)&Whs[(j + 1) * FOUT + tc * 8];
            float4 b11 = *(float4*)&Whs[(j + 1) * FOUT + tc * 8 + 4];
            float bv0[8] = {b00.x, b00.y, b00.z, b00.w, b01.x, b01.y, b01.z, b01.w};
            float bv1[8] = {b10.x, b10.y, b10.z, b10.w, b11.x, b11.y, b11.z, b11.w};

            #pragma unroll
            for (int r = 0; r < 8; r++) {
                sreg[r] += pr[r].x + pr[r].y;
                #pragma unroll
                for (int c = 0; c < 8; c++) {
                    acc[r][c] = fmaf(pr[r].x, bv0[c], acc[r][c]);
                    acc[r][c] = fmaf(pr[r].y, bv1[c], acc[r][c]);
                }
            }
        }
    }

    #pragma unroll
    for (int r = 0; r < 8; r++) {
        const float inv = 1.f / sreg[r];
        float* o = out + ((long)b * L + i0 + tr * 8 + r) * FOUT + tc * 8;
        float v[8];
        #pragma unroll
        for (int c = 0; c < 8; c++) {
            float x = acc[r][c] * inv;
            v[c] = x > 0.f ? x : expm1f(x);
        }
        float4 v0 = {v[0], v[1], v[2], v[3]};
        float4 v1 = {v[4], v[5], v[6], v[7]};
        *(float4*)o       = v0;
        *(float4*)(o + 4) = v1;
    }
}

// ---------------------------------------------------------------------------
extern "C" void kernel_launch(void* const* d_in, const int* in_sizes, int n_in,
                              void* d_out, int out_size) {
    const float* h    = (const float*)d_in[0];
    const float* W    = (const float*)d_in[1];
    const float* a    = (const float*)d_in[2];
    const float* bias = (const float*)d_in[3];
    const void*  adj  = d_in[4];
    float* out = (float*)d_out;

    k_detect<<<1, 32>>>((const unsigned int*)adj);
    k_gemm1<<<(B * L) / 128, 256>>>(h, W, a);

    const int smem = (64 * 128 + 128 * PS_LD + 128) * (int)sizeof(float);
    cudaFuncSetAttribute(k_attn, cudaFuncAttributeMaxDynamicSharedMemorySize, smem);
    dim3 grid(L / 128, B);
    k_attn<<<grid, 256, smem>>>(bias, adj, out);
}

// round 6
// speedup vs baseline: 1.7058x; 1.7058x over previous
#include <cuda_runtime.h>
#include <cuda_bf16.h>
#include <math.h>
#include <stdint.h>

#define B    128
#define L    512
#define FIN  128
#define FOUT 128
#define ALPHA 0.2f

// Scratch (device globals — no allocation allowed)
__device__ __nv_bfloat16 g_WhTh[(size_t)B * FOUT * L];  // Wh^T bf16 hi: [b][n][l]
__device__ __nv_bfloat16 g_WhTl[(size_t)B * FOUT * L];  // bf16 lo residual
__device__ float g_ei[B * L];
__device__ float g_ej[B * L];
__device__ int   g_maskKind;   // 0=int32, 1=uint8, 2=float32

// ============================ helpers ============================
__device__ __forceinline__ uint32_t smem_u32(const void* p) {
    uint32_t a;
    asm("{ .reg .u64 t; cvta.to.shared.u64 t, %1; cvt.u32.u64 %0, t; }"
        : "=r"(a) : "l"(p));
    return a;
}
__device__ __forceinline__ void ldsm_x4(uint32_t* r, uint32_t addr) {
    asm volatile("ldmatrix.sync.aligned.m8n8.x4.shared.b16 {%0,%1,%2,%3}, [%4];"
                 : "=r"(r[0]), "=r"(r[1]), "=r"(r[2]), "=r"(r[3]) : "r"(addr));
}
__device__ __forceinline__ void mma_bf16(float* c, const uint32_t* a,
                                         uint32_t b0, uint32_t b1) {
    asm volatile(
        "mma.sync.aligned.m16n8k16.row.col.f32.bf16.bf16.f32 "
        "{%0,%1,%2,%3}, {%4,%5,%6,%7}, {%8,%9}, {%0,%1,%2,%3};"
        : "+f"(c[0]), "+f"(c[1]), "+f"(c[2]), "+f"(c[3])
        : "r"(a[0]), "r"(a[1]), "r"(a[2]), "r"(a[3]), "r"(b0), "r"(b1));
}
__device__ __forceinline__ uint32_t pack_bf2(__nv_bfloat16 a, __nv_bfloat16 b) {
    return (uint32_t)__bfloat16_as_ushort(a) | ((uint32_t)__bfloat16_as_ushort(b) << 16);
}

// ---------------------------------------------------------------------------
// Kernel 0: detect adj_mask storage layout (bool dtype on device is unknown).
// ---------------------------------------------------------------------------
__global__ void k_detect(const unsigned int* __restrict__ m) {
    unsigned gt1 = 0, flt = 0;
    for (int i = threadIdx.x; i < 256; i += 32) {
        unsigned w = m[i];
        if (w == 0x3F800000u) flt = 1;
        else if (w > 1u)      gt1 = 1;
    }
    unsigned bft = __ballot_sync(0xFFFFFFFFu, flt);
    unsigned bgt = __ballot_sync(0xFFFFFFFFu, gt1);
    if (threadIdx.x == 0)
        g_maskKind = bft ? 2 : (bgt ? 1 : 0);
}

// ---------------------------------------------------------------------------
// Kernel 1: Wh = h @ W (fp32, exact).  Epilogue: (a) split Wh into bf16 hi/lo,
// stored TRANSPOSED [b][n][l] (B operand for HMMA); (b) exact ei/ej dots.
// ---------------------------------------------------------------------------
#define HT_LD 132

__global__ __launch_bounds__(256, 2) void k_gemm1(const float* __restrict__ h,
                                                  const float* __restrict__ W,
                                                  const float* __restrict__ a) {
    __shared__ float hsT[32][HT_LD];
    __shared__ float Ws[32][128];

    const int t  = threadIdx.x;
    const int tr = t >> 4;
    const int tc = t & 15;
    const long rowBase = (long)blockIdx.x * 128;

    float acc[8][8];
    #pragma unroll
    for (int r = 0; r < 8; r++)
        #pragma unroll
        for (int c = 0; c < 8; c++) acc[r][c] = 0.f;

    for (int kc = 0; kc < FIN; kc += 32) {
        __syncthreads();
        for (int l = t; l < 1024; l += 256) {
            int i = l >> 3, k4 = l & 7;
            float4 v = *(const float4*)(h + (rowBase + i) * FIN + kc + k4 * 4);
            hsT[k4 * 4 + 0][i] = v.x;
            hsT[k4 * 4 + 1][i] = v.y;
            hsT[k4 * 4 + 2][i] = v.z;
            hsT[k4 * 4 + 3][i] = v.w;
        }
        for (int l = t; l < 1024; l += 256) {
            int r = l >> 5, c4 = l & 31;
            *(float4*)&Ws[r][c4 * 4] = *(const float4*)(W + (kc + r) * FOUT + c4 * 4);
        }
        __syncthreads();

        #pragma unroll
        for (int k = 0; k < 32; k++) {
            float4 a0 = *(float4*)&hsT[k][tr * 8];
            float4 a1 = *(float4*)&hsT[k][tr * 8 + 4];
            float4 b0 = *(float4*)&Ws[k][tc * 8];
            float4 b1 = *(float4*)&Ws[k][tc * 8 + 4];
            float av[8] = {a0.x, a0.y, a0.z, a0.w, a1.x, a1.y, a1.z, a1.w};
            float bv[8] = {b0.x, b0.y, b0.z, b0.w, b1.x, b1.y, b1.z, b1.w};
            #pragma unroll
            for (int r = 0; r < 8; r++)
                #pragma unroll
                for (int c = 0; c < 8; c++)
                    acc[r][c] = fmaf(av[r], bv[c], acc[r][c]);
        }
    }

    // --- epilogue A: transposed bf16 hi/lo Wh ---
    const int bIdx  = (int)(rowBase >> 9);
    const int lBase = (int)(rowBase & 511);
    #pragma unroll
    for (int c = 0; c < 8; c++) {
        const int n = tc * 8 + c;
        __align__(16) __nv_bfloat16 hi[8], lo[8];
        #pragma unroll
        for (int r = 0; r < 8; r++) {
            float v = acc[r][c];
            hi[r] = __float2bfloat16(v);
            lo[r] = __float2bfloat16(v - __bfloat162float(hi[r]));
        }
        size_t off = (size_t)(bIdx * FOUT + n) * L + lBase + tr * 8;
        *(uint4*)(g_WhTh + off) = *(uint4*)hi;
        *(uint4*)(g_WhTl + off) = *(uint4*)lo;
    }

    // --- epilogue B: exact ei/ej ---
    float av1[8], av2[8];
    #pragma unroll
    for (int c = 0; c < 8; c++) {
        av1[c] = a[tc * 8 + c];
        av2[c] = a[FOUT + tc * 8 + c];
    }
    #pragma unroll
    for (int r = 0; r < 8; r++) {
        float s1 = 0.f, s2 = 0.f;
        #pragma unroll
        for (int c = 0; c < 8; c++) {
            s1 = fmaf(acc[r][c], av1[c], s1);
            s2 = fmaf(acc[r][c], av2[c], s2);
        }
        #pragma unroll
        for (int o = 8; o; o >>= 1) {
            s1 += __shfl_xor_sync(0xFFFFFFFFu, s1, o);
            s2 += __shfl_xor_sync(0xFFFFFFFFu, s2, o);
        }
        if (tc == 0) {
            g_ei[rowBase + tr * 8 + r] = s1;
            g_ej[rowBase + tr * 8 + r] = s2;
        }
    }
}

// ---------------------------------------------------------------------------
// Kernel 2: fused attention on HMMA (mma.sync m16n8k16 bf16, split hi/lo).
//  CTA = (128 i-rows, batch b), 8 j-tiles of 64.
//  Phase A per tile: warps 0-3 compute p rows exactly in fp32 (+row sums),
//    store bf16 hi/lo to smem; warps 4-7 copy pre-split Wh^T tile to smem.
//  Phase B: all 8 warps, warp w owns rows w*16..+15 x all 128 n.
//    ldmatrix A (p) + B (Wh^T), 3 mma chains: ph*wh + ph*wl + pl*wh.
//  Epilogue: divide by exact fp32 row sum, ELU, store.
// smem row stride 72 bf16 (144B) -> ldmatrix conflict-free.
// ---------------------------------------------------------------------------
#define PST 72                       // bf16 row stride
#define SM_PH 0
#define SM_PL 18432
#define SM_BH 36864
#define SM_BL 55296
#define SM_EJ 73728                  // 512 floats
#define SM_SS 75776                  // 128 floats
#define SM_TOTAL 76288

__global__ __launch_bounds__(256, 2) void k_attn(const float* __restrict__ bias,
                                                 const void* __restrict__ adj,
                                                 float* __restrict__ out) {
    extern __shared__ char smem[];
    const uint32_t sb = smem_u32(smem);

    const int t    = threadIdx.x;
    const int wid  = t >> 5;
    const int lane = t & 31;
    const int b    = blockIdx.y;
    const int i0   = blockIdx.x * 128;

    const int kind = g_maskKind;
    const int* adjI = (const int*)adj;
    const unsigned char* adjB = (const unsigned char*)adj;
    const float* adjF = (const float*)adj;

    float* ejs  = (float*)(smem + SM_EJ);
    float* ssum = (float*)(smem + SM_SS);
    if (t < 128) *(float4*)&ejs[t * 4] = *(const float4*)&g_ej[b * L + t * 4];

    float ei_m = 0.f, sum_m = 0.f;
    if (t < 128) ei_m = g_ei[b * L + i0 + t];

    float acc[16][4];
    #pragma unroll
    for (int n = 0; n < 16; n++)
        #pragma unroll
        for (int c = 0; c < 4; c++) acc[n][c] = 0.f;

    // fragment smem addresses (byte)
    const int aRow  = wid * 16 + (lane & 15);
    const int aKoff = (lane >> 4) * 16;                       // bytes
    const uint32_t aAddrH = sb + SM_PH + aRow * 144 + aKoff;
    const uint32_t aAddrL = sb + SM_PL + aRow * 144 + aKoff;
    const int bRow  = (lane & 7) + ((lane >> 4) << 3);        // n offset within 16
    const int bKoff = ((lane >> 3) & 1) * 16;                 // bytes
    const uint32_t bAddrH = sb + SM_BH + bRow * 144 + bKoff;
    const uint32_t bAddrL = sb + SM_BL + bRow * 144 + bKoff;

    for (int jt = 0; jt < 8; jt++) {
        const int j0 = jt * 64;
        __syncthreads();   // smem free (previous tile's fragment reads done)

        if (t < 128) {
            // ---- p-phase: row m = t, columns j0..j0+63, exact fp32 ----
            const int m = t;
            const float* bRowP = bias + ((size_t)b * L + i0 + m) * L + j0;
            const size_t adjRow = (size_t)(i0 + m) * L + j0;
            char* ph = smem + SM_PH + m * 144;
            char* pl = smem + SM_PL + m * 144;
            #pragma unroll
            for (int c4 = 0; c4 < 16; c4++) {
                const int j = c4 * 4;
                float4 bv = *(const float4*)(bRowP + j);
                bool m0, m1, m2, m3;
                if (kind == 0) {
                    int4 w = *(const int4*)(adjI + adjRow + j);
                    m0 = w.x != 0; m1 = w.y != 0; m2 = w.z != 0; m3 = w.w != 0;
                } else if (kind == 2) {
                    float4 w = *(const float4*)(adjF + adjRow + j);
                    m0 = w.x != 0.f; m1 = w.y != 0.f; m2 = w.z != 0.f; m3 = w.w != 0.f;
                } else {
                    uint32_t w = *(const uint32_t*)(adjB + adjRow + j);
                    m0 = (w & 0xFFu) != 0; m1 = (w & 0xFF00u) != 0;
                    m2 = (w & 0xFF0000u) != 0; m3 = (w & 0xFF000000u) != 0;
                }
                float x0 = ei_m + ejs[j0 + j];
                float x1 = ei_m + ejs[j0 + j + 1];
                float x2 = ei_m + ejs[j0 + j + 2];
                float x3 = ei_m + ejs[j0 + j + 3];
                x0 = (x0 > 0.f ? x0 : ALPHA * x0) + bv.x;
                x1 = (x1 > 0.f ? x1 : ALPHA * x1) + bv.y;
                x2 = (x2 > 0.f ? x2 : ALPHA * x2) + bv.z;
                x3 = (x3 > 0.f ? x3 : ALPHA * x3) + bv.w;
                float p0 = m0 ? __expf(x0) : 0.f;
                float p1 = m1 ? __expf(x1) : 0.f;
                float p2 = m2 ? __expf(x2) : 0.f;
                float p3 = m3 ? __expf(x3) : 0.f;
                sum_m += (p0 + p1) + (p2 + p3);
                __nv_bfloat16 h0 = __float2bfloat16(p0), h1 = __float2bfloat16(p1);
                __nv_bfloat16 h2 = __float2bfloat16(p2), h3 = __float2bfloat16(p3);
                uint2 hv = {pack_bf2(h0, h1), pack_bf2(h2, h3)};
                uint2 lv = {pack_bf2(__float2bfloat16(p0 - __bfloat162float(h0)),
                                     __float2bfloat16(p1 - __bfloat162float(h1))),
                            pack_bf2(__float2bfloat16(p2 - __bfloat162float(h2)),
                                     __float2bfloat16(p3 - __bfloat162float(h3)))};
                *(uint2*)(ph + j * 2) = hv;
                *(uint2*)(pl + j * 2) = lv;
            }
        } else {
            // ---- B copy: smem[n][0..63] <- g_WhT*[b][n][j0..j0+63] ----
            const int u = t - 128;
            const size_t bbase = (size_t)b * FOUT * L + j0;
            #pragma unroll
            for (int r = 0; r < 8; r++) {
                const int idx = u + 128 * r;
                const int n = idx >> 3, c = idx & 7;
                const size_t so = bbase + (size_t)n * L + c * 8;
                const int d = n * 144 + c * 16;
                *(uint4*)(smem + SM_BH + d) = *(const uint4*)(g_WhTh + so);
                *(uint4*)(smem + SM_BL + d) = *(const uint4*)(g_WhTl + so);
            }
        }
        __syncthreads();

        // ---- HMMA phase ----
        #pragma unroll
        for (int ks = 0; ks < 4; ks++) {
            uint32_t ah[4], al[4];
            ldsm_x4(ah, aAddrH + ks * 32);
            ldsm_x4(al, aAddrL + ks * 32);
            #pragma unroll
            for (int nt2 = 0; nt2 < 8; nt2++) {
                uint32_t bh[4], bl[4];
                ldsm_x4(bh, bAddrH + nt2 * 16 * 144 + ks * 32);
                ldsm_x4(bl, bAddrL + nt2 * 16 * 144 + ks * 32);
                mma_bf16(acc[nt2 * 2],     ah, bh[0], bh[1]);
                mma_bf16(acc[nt2 * 2 + 1], ah, bh[2], bh[3]);
                mma_bf16(acc[nt2 * 2],     ah, bl[0], bl[1]);
                mma_bf16(acc[nt2 * 2 + 1], ah, bl[2], bl[3]);
                mma_bf16(acc[nt2 * 2],     al, bh[0], bh[1]);
                mma_bf16(acc[nt2 * 2 + 1], al, bh[2], bh[3]);
            }
        }
    }

    if (t < 128) ssum[t] = sum_m;
    __syncthreads();

    // ---- epilogue: divide by row sum, ELU, store ----
    const int g  = lane >> 2;
    const int i2 = (lane & 3) * 2;
    const int r0 = wid * 16 + g;
    const int r1 = r0 + 8;
    const float inv0 = 1.f / ssum[r0];
    const float inv1 = 1.f / ssum[r1];
    float* o0 = out + ((size_t)b * L + i0 + r0) * FOUT;
    float* o1 = out + ((size_t)b * L + i0 + r1) * FOUT;
    #pragma unroll
    for (int nt = 0; nt < 16; nt++) {
        float v0 = acc[nt][0] * inv0, v1 = acc[nt][1] * inv0;
        float v2 = acc[nt][2] * inv1, v3 = acc[nt][3] * inv1;
        v0 = v0 > 0.f ? v0 : expm1f(v0);
        v1 = v1 > 0.f ? v1 : expm1f(v1);
        v2 = v2 > 0.f ? v2 : expm1f(v2);
        v3 = v3 > 0.f ? v3 : expm1f(v3);
        float2 w0 = {v0, v1}, w1 = {v2, v3};
        *(float2*)(o0 + nt * 8 + i2) = w0;
        *(float2*)(o1 + nt * 8 + i2) = w1;
    }
}

// ---------------------------------------------------------------------------
extern "C" void kernel_launch(void* const* d_in, const int* in_sizes, int n_in,
                              void* d_out, int out_size) {
    const float* h    = (const float*)d_in[0];
    const float* W    = (const float*)d_in[1];
    const float* a    = (const float*)d_in[2];
    const float* bias = (const float*)d_in[3];
    const void*  adj  = d_in[4];
    float* out = (float*)d_out;

    k_detect<<<1, 32>>>((const unsigned int*)adj);
    k_gemm1<<<(B * L) / 128, 256>>>(h, W, a);

    cudaFuncSetAttribute(k_attn, cudaFuncAttributeMaxDynamicSharedMemorySize, SM_TOTAL);
    dim3 grid(L / 128, B);
    k_attn<<<grid, 256, SM_TOTAL>>>(bias, adj, out);
}